// round 2
// baseline (speedup 1.0000x reference)
#include <cuda_runtime.h>
#include <cstdint>

// ============================================================================
// Problem constants
// ============================================================================
#define M_TOTAL   32768
#define N_TOTAL   1024
#define K_TOTAL   1024
#define THRESH    0.05f

// GEMM tiling
#define TILE_M    128
#define TILE_N    128
#define TILE_K    64            // int8 bytes per K-chunk
#define NUM_KC    (K_TOTAL / TILE_K)       // 16
#define STAGES    3
#define ROW_BYTES 80            // 64B data + 16B pad (bank-conflict-free fragments)
#define STAGE_BYTES ((TILE_M + TILE_N) * ROW_BYTES)   // 256*80 = 20480
#define SMEM_TOTAL  (STAGES * STAGE_BYTES)            // 61440

#define M_TILES   (M_TOTAL / TILE_M)   // 256
#define N_TILES   (N_TOTAL / TILE_N)   // 8

// ============================================================================
// Scratch (device globals — no runtime allocation allowed)
// ============================================================================
__device__ int8_t g_xq[(size_t)M_TOTAL * K_TOTAL];   // 32 MiB
__device__ int8_t g_wq[(size_t)N_TOTAL * K_TOTAL];   // 1 MiB

// ============================================================================
// Helpers
// ============================================================================
__device__ __forceinline__ uint32_t smem_u32(const void* p) {
    uint32_t a;
    asm("{ .reg .u64 t; cvta.to.shared.u64 t, %1; cvt.u32.u64 %0, t; }"
        : "=r"(a) : "l"(p));
    return a;
}

#define CP_ASYNC16(dst_u32, gsrc) \
    asm volatile("cp.async.cg.shared.global [%0], [%1], 16;" \
                 :: "r"(dst_u32), "l"(gsrc) : "memory")
#define CP_ASYNC_COMMIT() asm volatile("cp.async.commit_group;" ::: "memory")
#define CP_ASYNC_WAIT(n)  asm volatile("cp.async.wait_group %0;" :: "n"(n) : "memory")

__device__ __forceinline__ void mma_s8(int* c, const uint32_t* a, const uint32_t* b) {
    asm volatile(
        "mma.sync.aligned.m16n8k32.row.col.s32.s8.s8.s32 "
        "{%0,%1,%2,%3}, {%4,%5,%6,%7}, {%8,%9}, {%0,%1,%2,%3};"
        : "+r"(c[0]), "+r"(c[1]), "+r"(c[2]), "+r"(c[3])
        : "r"(a[0]), "r"(a[1]), "r"(a[2]), "r"(a[3]), "r"(b[0]), "r"(b[1]));
}

// ============================================================================
// Quantize: fp32 -> ternary int8 ({-1, 0, +1}), 16 elems/thread
// ============================================================================
__device__ __forceinline__ int8_t tq(float v) {
    return (fabsf(v) < THRESH) ? (int8_t)0 : (v > 0.f ? (int8_t)1 : (int8_t)-1);
}

__global__ __launch_bounds__(256) void quantize_kernel(
    const float* __restrict__ in, int8_t* __restrict__ out, int n16)
{
    int i = blockIdx.x * blockDim.x + threadIdx.x;
    if (i >= n16) return;
    const float4* in4 = (const float4*)in;
    int8_t r[16];
    #pragma unroll
    for (int j = 0; j < 4; j++) {
        float4 v = in4[i * 4 + j];
        r[j * 4 + 0] = tq(v.x);
        r[j * 4 + 1] = tq(v.y);
        r[j * 4 + 2] = tq(v.z);
        r[j * 4 + 3] = tq(v.w);
    }
    reinterpret_cast<int4*>(out)[i] = *reinterpret_cast<int4*>(r);
}

// ============================================================================
// GEMM: C[M,N] = Xq[M,K] @ Wq[N,K]^T  (int8 mma.sync, int32 accum, fp32 out)
// 256 threads = 8 warps, warp grid 4(M) x 2(N): each warp 32x64.
// ============================================================================
__global__ __launch_bounds__(256, 2) void ternary_gemm_kernel(float* __restrict__ out)
{
    extern __shared__ char smem[];
    const int tid  = threadIdx.x;
    const int lane = tid & 31;
    const int wid  = tid >> 5;
    const int wm   = wid & 3;    // 0..3  (M subtile)
    const int wn   = wid >> 2;   // 0..1  (N subtile)

    const int m0 = (int)(blockIdx.x >> 3) * TILE_M;   // n-tile fastest: L2 reuse of A
    const int n0 = (int)(blockIdx.x & 7) * TILE_N;

    const uint64_t xg = __cvta_generic_to_global(g_xq);
    const uint64_t wg = __cvta_generic_to_global(g_wq);

    // ---- stage loader: A rows [0,128) then B rows [128,256), 4 x 16B per thread
    auto load_stage = [&](int kc, int s) {
        uint32_t sb = smem_u32(smem + s * STAGE_BYTES);
        #pragma unroll
        for (int t = 0; t < 2; t++) {              // A: rows 0..127
            int i = tid + t * 256;
            int row = i >> 2, seg = i & 3;
            uint64_t src = xg + (uint64_t)(m0 + row) * K_TOTAL + kc * TILE_K + seg * 16;
            CP_ASYNC16(sb + row * ROW_BYTES + seg * 16, src);
        }
        #pragma unroll
        for (int t = 0; t < 2; t++) {              // B: rows 128..255
            int i = tid + t * 256;
            int row = i >> 2, seg = i & 3;
            uint64_t src = wg + (uint64_t)(n0 + row) * K_TOTAL + kc * TILE_K + seg * 16;
            CP_ASYNC16(sb + (TILE_M + row) * ROW_BYTES + seg * 16, src);
        }
        CP_ASYNC_COMMIT();
    };

    int acc[2][8][4];
    #pragma unroll
    for (int mi = 0; mi < 2; mi++)
        #pragma unroll
        for (int ni = 0; ni < 8; ni++)
            #pragma unroll
            for (int q = 0; q < 4; q++) acc[mi][ni][q] = 0;

    // Prologue: fill STAGES-1 stages
    load_stage(0, 0);
    load_stage(1, 1);

    for (int kc = 0; kc < NUM_KC; kc++) {
        if (kc + STAGES - 1 < NUM_KC) CP_ASYNC_WAIT(STAGES - 2);
        else                          CP_ASYNC_WAIT(0);
        __syncthreads();

        const char* aS = smem + (kc % STAGES) * STAGE_BYTES;
        const char* bS = aS + TILE_M * ROW_BYTES;

        #pragma unroll
        for (int kk = 0; kk < 2; kk++) {           // two k=32 steps per chunk
            const int kb = kk * 32 + (lane & 3) * 4;
            const int rr = lane >> 2;

            uint32_t a[2][4];
            #pragma unroll
            for (int mi = 0; mi < 2; mi++) {
                const char* p = aS + (wm * 32 + mi * 16 + rr) * ROW_BYTES + kb;
                a[mi][0] = *(const uint32_t*)(p);
                a[mi][1] = *(const uint32_t*)(p + 8 * ROW_BYTES);
                a[mi][2] = *(const uint32_t*)(p + 16);
                a[mi][3] = *(const uint32_t*)(p + 8 * ROW_BYTES + 16);
            }
            uint32_t b[8][2];
            #pragma unroll
            for (int ni = 0; ni < 8; ni++) {
                const char* p = bS + (wn * 64 + ni * 8 + rr) * ROW_BYTES + kb;
                b[ni][0] = *(const uint32_t*)(p);
                b[ni][1] = *(const uint32_t*)(p + 16);
            }
            #pragma unroll
            for (int mi = 0; mi < 2; mi++)
                #pragma unroll
                for (int ni = 0; ni < 8; ni++)
                    mma_s8(acc[mi][ni], a[mi], b[ni]);
        }

        // refill the stage consumed at iter kc-1 (safe: all warps passed the
        // barrier above, which orders their reads of that stage)
        if (kc + STAGES - 1 < NUM_KC)
            load_stage(kc + STAGES - 1, (kc + STAGES - 1) % STAGES);
    }

    // ---- Epilogue: int32 -> fp32 (exact; |acc| <= 1024), float2 stores
    //      4-lane groups cover 8 consecutive cols = one full 32B sector.
    #pragma unroll
    for (int mi = 0; mi < 2; mi++) {
        const int r = m0 + wm * 32 + mi * 16 + (lane >> 2);
        #pragma unroll
        for (int ni = 0; ni < 8; ni++) {
            const int c = n0 + wn * 64 + ni * 8 + (lane & 3) * 2;
            float2 v0 = make_float2((float)acc[mi][ni][0], (float)acc[mi][ni][1]);
            float2 v1 = make_float2((float)acc[mi][ni][2], (float)acc[mi][ni][3]);
            *(float2*)(out + (size_t)r * N_TOTAL + c)       = v0;
            *(float2*)(out + (size_t)(r + 8) * N_TOTAL + c) = v1;
        }
    }
}

// ============================================================================
// Launch
// ============================================================================
extern "C" void kernel_launch(void* const* d_in, const int* in_sizes, int n_in,
                              void* d_out, int out_size)
{
    const float* x = (const float*)d_in[0];
    const float* w = (const float*)d_in[1];
    float* out = (float*)d_out;

    int8_t* xq_p = nullptr;
    int8_t* wq_p = nullptr;
    cudaGetSymbolAddress((void**)&xq_p, g_xq);
    cudaGetSymbolAddress((void**)&wq_p, g_wq);

    // Quantize x and weight to ternary int8
    {
        int n16 = (M_TOTAL * K_TOTAL) / 16;            // 2M
        quantize_kernel<<<n16 / 256, 256>>>(x, xq_p, n16);
    }
    {
        int n16 = (N_TOTAL * K_TOTAL) / 16;            // 64K
        quantize_kernel<<<n16 / 256, 256>>>(w, wq_p, n16);
    }

    // GEMM
    static bool attr_set = false;
    if (!attr_set) {
        cudaFuncSetAttribute(ternary_gemm_kernel,
                             cudaFuncAttributeMaxDynamicSharedMemorySize, SMEM_TOTAL);
        attr_set = true;
    }
    ternary_gemm_kernel<<<M_TILES * N_TILES, 256, SMEM_TOTAL>>>(out);
}

// round 3
// speedup vs baseline: 1.0264x; 1.0264x over previous
#include <cuda_runtime.h>
#include <cstdint>

// ============================================================================
// Problem constants
// ============================================================================
#define M_TOTAL   32768
#define N_TOTAL   1024
#define K_TOTAL   1024
#define THRESH    0.05f

// GEMM tiling
#define TILE_M    128
#define TILE_N    128
#define TILE_K    64            // int8 bytes per K-chunk
#define NUM_KC    (K_TOTAL / TILE_K)       // 16
#define STAGES    3
#define ROW_BYTES 80            // 64B data + 16B pad (bank-conflict-free)
#define STAGE_BYTES ((TILE_M + TILE_N) * ROW_BYTES)   // 20480
#define SMEM_TOTAL  (STAGES * STAGE_BYTES)            // 61440

#define M_TILES   (M_TOTAL / TILE_M)   // 256
#define N_TILES   (N_TOTAL / TILE_N)   // 8

// ============================================================================
// Scratch (device globals — no runtime allocation allowed)
// ============================================================================
__device__ int8_t g_xq[(size_t)M_TOTAL * K_TOTAL];   // 32 MiB
__device__ int8_t g_wq[(size_t)N_TOTAL * K_TOTAL];   // 1 MiB

// ============================================================================
// Helpers
// ============================================================================
__device__ __forceinline__ uint32_t smem_u32(const void* p) {
    uint32_t a;
    asm("{ .reg .u64 t; cvta.to.shared.u64 t, %1; cvt.u32.u64 %0, t; }"
        : "=r"(a) : "l"(p));
    return a;
}

#define CP_ASYNC16(dst_u32, gsrc) \
    asm volatile("cp.async.cg.shared.global [%0], [%1], 16;" \
                 :: "r"(dst_u32), "l"(gsrc) : "memory")
#define CP_ASYNC_COMMIT() asm volatile("cp.async.commit_group;" ::: "memory")
#define CP_ASYNC_WAIT(n)  asm volatile("cp.async.wait_group %0;" :: "n"(n) : "memory")

__device__ __forceinline__ void mma_s8(int* c, const uint32_t* a, const uint32_t* b) {
    asm volatile(
        "mma.sync.aligned.m16n8k32.row.col.s32.s8.s8.s32 "
        "{%0,%1,%2,%3}, {%4,%5,%6,%7}, {%8,%9}, {%0,%1,%2,%3};"
        : "+r"(c[0]), "+r"(c[1]), "+r"(c[2]), "+r"(c[3])
        : "r"(a[0]), "r"(a[1]), "r"(a[2]), "r"(a[3]), "r"(b[0]), "r"(b[1]));
}

__device__ __forceinline__ void ldsm_x4(uint32_t* r, uint32_t addr) {
    asm volatile("ldmatrix.sync.aligned.m8n8.x4.shared.b16 {%0,%1,%2,%3}, [%4];"
        : "=r"(r[0]), "=r"(r[1]), "=r"(r[2]), "=r"(r[3]) : "r"(addr));
}

// ============================================================================
// Quantize: fp32 -> ternary int8 ({-1, 0, +1}), 16 elems/thread
// ============================================================================
__device__ __forceinline__ int8_t tq(float v) {
    return (fabsf(v) < THRESH) ? (int8_t)0 : (v > 0.f ? (int8_t)1 : (int8_t)-1);
}

__global__ __launch_bounds__(256) void quantize_kernel(
    const float* __restrict__ in, int8_t* __restrict__ out, int n16)
{
    int i = blockIdx.x * blockDim.x + threadIdx.x;
    if (i >= n16) return;
    const float4* in4 = (const float4*)in;
    int8_t r[16];
    #pragma unroll
    for (int j = 0; j < 4; j++) {
        float4 v = in4[i * 4 + j];
        r[j * 4 + 0] = tq(v.x);
        r[j * 4 + 1] = tq(v.y);
        r[j * 4 + 2] = tq(v.z);
        r[j * 4 + 3] = tq(v.w);
    }
    reinterpret_cast<int4*>(out)[i] = *reinterpret_cast<int4*>(r);
}

// ============================================================================
// GEMM: C[M,N] = Xq[M,K] @ Wq[N,K]^T  (int8 mma.sync, int32 accum, fp32 out)
// 256 threads = 8 warps, warp grid 4(M) x 2(N): each warp 32x64.
// Fragment loads via ldmatrix.x4 (12 per warp per K-chunk).
// ============================================================================
__global__ __launch_bounds__(256, 2) void ternary_gemm_kernel(float* __restrict__ out)
{
    extern __shared__ char smem[];
    const int tid  = threadIdx.x;
    const int lane = tid & 31;
    const int wid  = tid >> 5;
    const int wm   = wid & 3;    // 0..3  (M subtile, 32 rows)
    const int wn   = wid >> 2;   // 0..1  (N subtile, 64 cols)

    const int m0 = (int)(blockIdx.x >> 3) * TILE_M;   // n-tile fastest: L2 reuse of A
    const int n0 = (int)(blockIdx.x & 7) * TILE_N;

    const uint64_t xg = __cvta_generic_to_global(g_xq);
    const uint64_t wg = __cvta_generic_to_global(g_wq);
    const uint32_t sbase = smem_u32(smem);

    // Per-lane ldmatrix address offsets.
    // A (row-major, m16 x k32 fragment via x4):
    //   matrices: (rows0-7,k0-15),(rows8-15,k0-15),(rows0-7,k16-31),(rows8-15,k16-31)
    const int g8 = lane >> 3, t8 = lane & 7;
    const uint32_t a_lane = (uint32_t)((t8 + ((g8 & 1) << 3)) * ROW_BYTES + ((g8 >> 1) << 4));
    // B (col-rows, two n8 x k32 fragments via x4):
    //   matrices: (cols0-7,k0-15),(cols0-7,k16-31),(cols8-15,k0-15),(cols8-15,k16-31)
    const uint32_t b_lane = (uint32_t)((t8 + ((g8 >> 1) << 3)) * ROW_BYTES + ((g8 & 1) << 4));

    // ---- stage loader: A rows [0,128) then B rows [128,256), 4 x 16B per thread
    auto load_stage = [&](int kc, int s) {
        uint32_t sb = sbase + s * STAGE_BYTES;
        #pragma unroll
        for (int t = 0; t < 2; t++) {              // A: rows 0..127
            int i = tid + t * 256;
            int row = i >> 2, seg = i & 3;
            uint64_t src = xg + (uint64_t)(m0 + row) * K_TOTAL + kc * TILE_K + seg * 16;
            CP_ASYNC16(sb + row * ROW_BYTES + seg * 16, src);
        }
        #pragma unroll
        for (int t = 0; t < 2; t++) {              // B: rows 128..255
            int i = tid + t * 256;
            int row = i >> 2, seg = i & 3;
            uint64_t src = wg + (uint64_t)(n0 + row) * K_TOTAL + kc * TILE_K + seg * 16;
            CP_ASYNC16(sb + (TILE_M + row) * ROW_BYTES + seg * 16, src);
        }
        CP_ASYNC_COMMIT();
    };

    int acc[2][8][4];
    #pragma unroll
    for (int mi = 0; mi < 2; mi++)
        #pragma unroll
        for (int ni = 0; ni < 8; ni++)
            #pragma unroll
            for (int q = 0; q < 4; q++) acc[mi][ni][q] = 0;

    // Prologue: fill STAGES-1 stages
    load_stage(0, 0);
    load_stage(1, 1);

    for (int kc = 0; kc < NUM_KC; kc++) {
        if (kc + STAGES - 1 < NUM_KC) CP_ASYNC_WAIT(STAGES - 2);
        else                          CP_ASYNC_WAIT(0);
        __syncthreads();

        const uint32_t stage = sbase + (kc % STAGES) * STAGE_BYTES;
        const uint32_t sa = stage + (uint32_t)(wm * 32) * ROW_BYTES + a_lane;
        const uint32_t sbB = stage + (uint32_t)(TILE_M + wn * 64) * ROW_BYTES + b_lane;

        #pragma unroll
        for (int kk = 0; kk < 2; kk++) {           // two k=32 steps per chunk
            const uint32_t ko = (uint32_t)(kk * 32);

            uint32_t a[2][4];
            ldsm_x4(a[0], sa + ko);                        // rows wm*32 +  0..15
            ldsm_x4(a[1], sa + 16 * ROW_BYTES + ko);       // rows wm*32 + 16..31

            uint32_t b[4][4];                              // 4 pairs of n8 frags
            #pragma unroll
            for (int p = 0; p < 4; p++)
                ldsm_x4(b[p], sbB + (uint32_t)(p * 16) * ROW_BYTES + ko);

            #pragma unroll
            for (int mi = 0; mi < 2; mi++)
                #pragma unroll
                for (int ni = 0; ni < 8; ni++)
                    mma_s8(acc[mi][ni], a[mi], &b[ni >> 1][(ni & 1) * 2]);
        }

        // refill the stage consumed at iter kc-1 (all warps passed the barrier)
        if (kc + STAGES - 1 < NUM_KC)
            load_stage(kc + STAGES - 1, (kc + STAGES - 1) % STAGES);
    }

    // ---- Epilogue: int32 -> fp32 (exact; |acc| <= 1024), float2 stores
    #pragma unroll
    for (int mi = 0; mi < 2; mi++) {
        const int r = m0 + wm * 32 + mi * 16 + (lane >> 2);
        #pragma unroll
        for (int ni = 0; ni < 8; ni++) {
            const int c = n0 + wn * 64 + ni * 8 + (lane & 3) * 2;
            float2 v0 = make_float2((float)acc[mi][ni][0], (float)acc[mi][ni][1]);
            float2 v1 = make_float2((float)acc[mi][ni][2], (float)acc[mi][ni][3]);
            *(float2*)(out + (size_t)r * N_TOTAL + c)       = v0;
            *(float2*)(out + (size_t)(r + 8) * N_TOTAL + c) = v1;
        }
    }
}

// ============================================================================
// Launch
// ============================================================================
extern "C" void kernel_launch(void* const* d_in, const int* in_sizes, int n_in,
                              void* d_out, int out_size)
{
    const float* x = (const float*)d_in[0];
    const float* w = (const float*)d_in[1];
    float* out = (float*)d_out;

    int8_t* xq_p = nullptr;
    int8_t* wq_p = nullptr;
    cudaGetSymbolAddress((void**)&xq_p, g_xq);
    cudaGetSymbolAddress((void**)&wq_p, g_wq);

    // Quantize x and weight to ternary int8
    {
        int n16 = (M_TOTAL * K_TOTAL) / 16;            // 2M
        quantize_kernel<<<n16 / 256, 256>>>(x, xq_p, n16);
    }
    {
        int n16 = (N_TOTAL * K_TOTAL) / 16;            // 64K
        quantize_kernel<<<n16 / 256, 256>>>(w, wq_p, n16);
    }

    // GEMM
    static bool attr_set = false;
    if (!attr_set) {
        cudaFuncSetAttribute(ternary_gemm_kernel,
                             cudaFuncAttributeMaxDynamicSharedMemorySize, SMEM_TOTAL);
        attr_set = true;
    }
    ternary_gemm_kernel<<<M_TILES * N_TILES, 256, SMEM_TOTAL>>>(out);
}

// round 5
// speedup vs baseline: 1.1665x; 1.1365x over previous
#include <cuda_runtime.h>
#include <cstdint>

// ============================================================================
// Problem constants
// ============================================================================
#define M_TOTAL   32768
#define N_TOTAL   1024
#define K_TOTAL   1024
#define THRESH    0.05f

// ---- M split between engines
#define M_MMA     16384                 // rows via mma.sync (tensor pipe)
#define M_POPC    16384                 // rows via popcount (alu pipe)
#define NWORDS    (K_TOTAL / 32)        // 32 packed words per row

// ---- mma engine tiling
#define TILE_M    128
#define TILE_N    128
#define TILE_K    64
#define NUM_KC    (K_TOTAL / TILE_K)    // 16
#define STAGES    3
#define ROW_BYTES 80
#define STAGE_BYTES ((TILE_M + TILE_N) * ROW_BYTES)   // 20480
#define SMEM_TOTAL  (STAGES * STAGE_BYTES)            // 61440
#define MMA_CTAS  ((M_MMA / TILE_M) * (N_TOTAL / TILE_N))   // 128*8 = 1024

// ---- popc engine tiling: CTA 64M x 64N, 256 thr, thread 4x4
#define PTILE_M   64
#define PTILE_N   64
#define POPC_CTAS ((M_POPC / PTILE_M) * (N_TOTAL / PTILE_N)) // 256*16 = 4096

#define TOTAL_CTAS (MMA_CTAS + POPC_CTAS)   // 5120 (1 mma per 4 popc)

// ============================================================================
// Scratch (device globals — no runtime allocation)
// ============================================================================
__device__ int8_t g_xq[(size_t)M_MMA * K_TOTAL];     // 16 MiB (mma rows)
__device__ int8_t g_wq[(size_t)N_TOTAL * K_TOTAL];   // 1 MiB
__device__ uint2  g_xpk[NWORDS * M_POPC];            // 4 MiB, word-major [w][r]
__device__ uint2  g_wpk[NWORDS * N_TOTAL];           // 256 KiB, word-major [w][c]

// ============================================================================
// Helpers
// ============================================================================
__device__ __forceinline__ uint32_t smem_u32(const void* p) {
    uint32_t a;
    asm("{ .reg .u64 t; cvta.to.shared.u64 t, %1; cvt.u32.u64 %0, t; }"
        : "=r"(a) : "l"(p));
    return a;
}

#define CP_ASYNC16(dst_u32, gsrc) \
    asm volatile("cp.async.cg.shared.global [%0], [%1], 16;" \
                 :: "r"(dst_u32), "l"(gsrc) : "memory")
#define CP_ASYNC_COMMIT() asm volatile("cp.async.commit_group;" ::: "memory")
#define CP_ASYNC_WAIT(n)  asm volatile("cp.async.wait_group %0;" :: "n"(n) : "memory")

__device__ __forceinline__ void mma_s8(int* c, const uint32_t* a, const uint32_t* b) {
    asm volatile(
        "mma.sync.aligned.m16n8k32.row.col.s32.s8.s8.s32 "
        "{%0,%1,%2,%3}, {%4,%5,%6,%7}, {%8,%9}, {%0,%1,%2,%3};"
        : "+r"(c[0]), "+r"(c[1]), "+r"(c[2]), "+r"(c[3])
        : "r"(a[0]), "r"(a[1]), "r"(a[2]), "r"(a[3]), "r"(b[0]), "r"(b[1]));
}

__device__ __forceinline__ void ldsm_x4(uint32_t* r, uint32_t addr) {
    asm volatile("ldmatrix.sync.aligned.m8n8.x4.shared.b16 {%0,%1,%2,%3}, [%4];"
        : "=r"(r[0]), "=r"(r[1]), "=r"(r[2]), "=r"(r[3]) : "r"(addr));
}

__device__ __forceinline__ int8_t tq(float v) {
    return (fabsf(v) < THRESH) ? (int8_t)0 : (v > 0.f ? (int8_t)1 : (int8_t)-1);
}

// ============================================================================
// Quantize (int8, for mma rows) and bit-pack (for popc rows / weights)
// ============================================================================
__global__ __launch_bounds__(256) void quantize_kernel(
    const float* __restrict__ in, int8_t* __restrict__ out, int n16)
{
    int i = blockIdx.x * blockDim.x + threadIdx.x;
    if (i >= n16) return;
    const float4* in4 = (const float4*)in;
    int8_t r[16];
    #pragma unroll
    for (int j = 0; j < 4; j++) {
        float4 v = in4[i * 4 + j];
        r[j * 4 + 0] = tq(v.x);
        r[j * 4 + 1] = tq(v.y);
        r[j * 4 + 2] = tq(v.z);
        r[j * 4 + 3] = tq(v.w);
    }
    reinterpret_cast<int4*>(out)[i] = *reinterpret_cast<int4*>(r);
}

// Pack 32 floats -> (e,n) masks; word-major output pk[w*rows + r].
// in_row0: first source row; rows: number of rows to pack.
__global__ __launch_bounds__(256) void pack_kernel(
    const float* __restrict__ in, uint2* __restrict__ pk, int in_row0, int rows)
{
    int t = blockIdx.x * blockDim.x + threadIdx.x;
    if (t >= rows * NWORDS) return;
    int r = t % rows;          // row fastest -> coalesced writes
    int w = t / rows;
    const float4* p = (const float4*)(in + (size_t)(in_row0 + r) * K_TOTAL + w * 32);
    uint32_t e = 0, n = 0;
    #pragma unroll
    for (int j = 0; j < 8; j++) {
        float4 v = p[j];
        float f[4] = {v.x, v.y, v.z, v.w};
        #pragma unroll
        for (int q = 0; q < 4; q++) {
            uint32_t nz = (fabsf(f[q]) >= THRESH) ? 1u : 0u;
            uint32_t ng = (nz && f[q] < 0.f) ? 1u : 0u;
            e |= nz << (j * 4 + q);
            n |= ng << (j * 4 + q);
        }
    }
    pk[(size_t)w * rows + r] = make_uint2(e, n);
}

// ============================================================================
// Engine 1: mma.sync int8 CTA (rows [0, M_MMA))
// ============================================================================
__device__ __forceinline__ void mma_cta(int idx, char* smem, float* __restrict__ out)
{
    const int tid  = threadIdx.x;
    const int lane = tid & 31;
    const int wid  = tid >> 5;
    const int wm   = wid & 3;
    const int wn   = wid >> 2;

    const int m0 = (idx >> 3) * TILE_M;
    const int n0 = (idx & 7) * TILE_N;

    const uint64_t xg = __cvta_generic_to_global(g_xq);
    const uint64_t wg = __cvta_generic_to_global(g_wq);
    const uint32_t sbase = smem_u32(smem);

    const int g8 = lane >> 3, t8 = lane & 7;
    const uint32_t a_lane = (uint32_t)((t8 + ((g8 & 1) << 3)) * ROW_BYTES + ((g8 >> 1) << 4));
    const uint32_t b_lane = (uint32_t)((t8 + ((g8 >> 1) << 3)) * ROW_BYTES + ((g8 & 1) << 4));

    auto load_stage = [&](int kc, int s) {
        uint32_t sb = sbase + s * STAGE_BYTES;
        #pragma unroll
        for (int t = 0; t < 2; t++) {
            int i = tid + t * 256;
            int row = i >> 2, seg = i & 3;
            uint64_t src = xg + (uint64_t)(m0 + row) * K_TOTAL + kc * TILE_K + seg * 16;
            CP_ASYNC16(sb + row * ROW_BYTES + seg * 16, src);
        }
        #pragma unroll
        for (int t = 0; t < 2; t++) {
            int i = tid + t * 256;
            int row = i >> 2, seg = i & 3;
            uint64_t src = wg + (uint64_t)(n0 + row) * K_TOTAL + kc * TILE_K + seg * 16;
            CP_ASYNC16(sb + (TILE_M + row) * ROW_BYTES + seg * 16, src);
        }
        CP_ASYNC_COMMIT();
    };

    int acc[2][8][4];
    #pragma unroll
    for (int mi = 0; mi < 2; mi++)
        #pragma unroll
        for (int ni = 0; ni < 8; ni++)
            #pragma unroll
            for (int q = 0; q < 4; q++) acc[mi][ni][q] = 0;

    load_stage(0, 0);
    load_stage(1, 1);

    for (int kc = 0; kc < NUM_KC; kc++) {
        if (kc + STAGES - 1 < NUM_KC) CP_ASYNC_WAIT(STAGES - 2);
        else                          CP_ASYNC_WAIT(0);
        __syncthreads();

        const uint32_t stage = sbase + (kc % STAGES) * STAGE_BYTES;
        const uint32_t sa  = stage + (uint32_t)(wm * 32) * ROW_BYTES + a_lane;
        const uint32_t sbB = stage + (uint32_t)(TILE_M + wn * 64) * ROW_BYTES + b_lane;

        #pragma unroll
        for (int kk = 0; kk < 2; kk++) {
            const uint32_t ko = (uint32_t)(kk * 32);
            uint32_t a[2][4];
            ldsm_x4(a[0], sa + ko);
            ldsm_x4(a[1], sa + 16 * ROW_BYTES + ko);
            uint32_t b[4][4];
            #pragma unroll
            for (int p = 0; p < 4; p++)
                ldsm_x4(b[p], sbB + (uint32_t)(p * 16) * ROW_BYTES + ko);
            #pragma unroll
            for (int mi = 0; mi < 2; mi++)
                #pragma unroll
                for (int ni = 0; ni < 8; ni++)
                    mma_s8(acc[mi][ni], a[mi], &b[ni >> 1][(ni & 1) * 2]);
        }

        if (kc + STAGES - 1 < NUM_KC)
            load_stage(kc + STAGES - 1, (kc + STAGES - 1) % STAGES);
    }

    #pragma unroll
    for (int mi = 0; mi < 2; mi++) {
        const int r = m0 + wm * 32 + mi * 16 + (lane >> 2);
        #pragma unroll
        for (int ni = 0; ni < 8; ni++) {
            const int c = n0 + wn * 64 + ni * 8 + (lane & 3) * 2;
            float2 v0 = make_float2((float)acc[mi][ni][0], (float)acc[mi][ni][1]);
            float2 v1 = make_float2((float)acc[mi][ni][2], (float)acc[mi][ni][3]);
            *(float2*)(out + (size_t)r * N_TOTAL + c)       = v0;
            *(float2*)(out + (size_t)(r + 8) * N_TOTAL + c) = v1;
        }
    }
}

// ============================================================================
// Engine 2: bit-packed popcount CTA (rows [M_MMA, M_TOTAL))
// 64x64 tile, 256 threads (16x16), thread tile 4x4, full K resident in SMEM.
// contribution per word-pair: popc(xe&we) - 2*popc((xe&we)&(xn^wn))
// ============================================================================
__device__ __forceinline__ void popc_cta(int idx, char* smem, float* __restrict__ out)
{
    const int tid = threadIdx.x;
    const int tx = tid & 15;
    const int ty = tid >> 4;

    const int mt = idx >> 4;           // 0..255
    const int nt = idx & 15;           // 0..15
    const int m0 = mt * PTILE_M;       // row offset within popc rows
    const int n0 = nt * PTILE_N;

    const uint64_t xg = __cvta_generic_to_global(g_xpk);
    const uint64_t wg = __cvta_generic_to_global(g_wpk);
    const uint32_t sx = smem_u32(smem);               // xs: [w][64] uint2 = 16KB
    const uint32_t sw = sx + NWORDS * PTILE_M * 8;    // ws: [w][64] uint2 = 16KB

    // Load both tiles (32KB) with cp.async; layout is contiguous per word-run.
    #pragma unroll
    for (int i = 0; i < 4; i++) {
        int c = tid + i * 256;          // 1024 chunks of 16B for xs
        int w = c >> 5, o = c & 31;
        uint64_t src = xg + ((uint64_t)w * M_POPC + m0) * 8 + o * 16;
        CP_ASYNC16(sx + c * 16, src);
    }
    #pragma unroll
    for (int i = 0; i < 4; i++) {
        int c = tid + i * 256;          // 1024 chunks for ws
        int w = c >> 5, o = c & 31;
        uint64_t src = wg + ((uint64_t)w * N_TOTAL + n0) * 8 + o * 16;
        CP_ASYNC16(sw + c * 16, src);
    }
    CP_ASYNC_COMMIT();
    CP_ASYNC_WAIT(0);
    __syncthreads();

    int accE[4][4], accD[4][4];
    #pragma unroll
    for (int i = 0; i < 4; i++)
        #pragma unroll
        for (int j = 0; j < 4; j++) { accE[i][j] = 0; accD[i][j] = 0; }

    #pragma unroll 4
    for (int w = 0; w < NWORDS; w++) {
        // 4 x-rows (ty*4..+3): two 16B loads; .x/.z = e, .y/.w = n
        uint4 xa = *(const uint4*)(smem + (sx - smem_u32(smem)) + w * 512 + ty * 32);
        uint4 xb = *(const uint4*)(smem + (sx - smem_u32(smem)) + w * 512 + ty * 32 + 16);
        uint4 wa = *(const uint4*)(smem + (sw - smem_u32(smem)) + w * 512 + tx * 32);
        uint4 wb = *(const uint4*)(smem + (sw - smem_u32(smem)) + w * 512 + tx * 32 + 16);
        uint32_t xe[4] = {xa.x, xa.z, xb.x, xb.z};
        uint32_t xn[4] = {xa.y, xa.w, xb.y, xb.w};
        uint32_t we[4] = {wa.x, wa.z, wb.x, wb.z};
        uint32_t wn[4] = {wa.y, wa.w, wb.y, wb.w};
        #pragma unroll
        for (int i = 0; i < 4; i++) {
            #pragma unroll
            for (int j = 0; j < 4; j++) {
                uint32_t t = xe[i] & we[j];
                uint32_t d = t & (xn[i] ^ wn[j]);    // single LOP3
                accE[i][j] += __popc(t);
                accD[i][j] += __popc(d);
            }
        }
    }

    #pragma unroll
    for (int i = 0; i < 4; i++) {
        const int r = M_MMA + m0 + ty * 4 + i;
        float4 v;
        v.x = (float)(accE[i][0] - 2 * accD[i][0]);
        v.y = (float)(accE[i][1] - 2 * accD[i][1]);
        v.z = (float)(accE[i][2] - 2 * accD[i][2]);
        v.w = (float)(accE[i][3] - 2 * accD[i][3]);
        *(float4*)(out + (size_t)r * N_TOTAL + n0 + tx * 4) = v;
    }
}

// ============================================================================
// Fused GEMM: interleave 1 mma CTA per 4 popc CTAs (equal work per group)
// ============================================================================
__global__ __launch_bounds__(256, 2) void ternary_gemm_kernel(float* __restrict__ out)
{
    extern __shared__ char smem[];
    const int bid = (int)blockIdx.x;
    const int q = bid / 5;
    const int r = bid - q * 5;
    if (r == 0) mma_cta(q, smem, out);          // q in [0, 1024)
    else        popc_cta(4 * q + (r - 1), smem, out);  // in [0, 4096)
}

// ============================================================================
// Launch
// ============================================================================
extern "C" void kernel_launch(void* const* d_in, const int* in_sizes, int n_in,
                              void* d_out, int out_size)
{
    const float* x = (const float*)d_in[0];
    const float* w = (const float*)d_in[1];
    float* out = (float*)d_out;

    int8_t* xq_p = nullptr;  int8_t* wq_p = nullptr;
    uint2*  xpk_p = nullptr; uint2*  wpk_p = nullptr;
    cudaGetSymbolAddress((void**)&xq_p, g_xq);
    cudaGetSymbolAddress((void**)&wq_p, g_wq);
    cudaGetSymbolAddress((void**)&xpk_p, g_xpk);
    cudaGetSymbolAddress((void**)&wpk_p, g_wpk);

    // mma operands: int8 quantize (x rows [0, M_MMA), full w)
    {
        int n16 = (M_MMA * K_TOTAL) / 16;               // 1M
        quantize_kernel<<<n16 / 256, 256>>>(x, xq_p, n16);
    }
    {
        int n16 = (N_TOTAL * K_TOTAL) / 16;             // 64K
        quantize_kernel<<<n16 / 256, 256>>>(w, wq_p, n16);
    }
    // popc operands: bit-pack (x rows [M_MMA, M_TOTAL), full w)
    {
        int tot = M_POPC * NWORDS;                       // 512K
        pack_kernel<<<(tot + 255) / 256, 256>>>(x, xpk_p, M_MMA, M_POPC);
    }
    {
        int tot = N_TOTAL * NWORDS;                      // 32K
        pack_kernel<<<(tot + 255) / 256, 256>>>(w, wpk_p, 0, N_TOTAL);
    }

    static bool attr_set = false;
    if (!attr_set) {
        cudaFuncSetAttribute(ternary_gemm_kernel,
                             cudaFuncAttributeMaxDynamicSharedMemorySize, SMEM_TOTAL);
        attr_set = true;
    }
    ternary_gemm_kernel<<<TOTAL_CTAS, 256, SMEM_TOTAL>>>(out);
}